// round 15
// baseline (speedup 1.0000x reference)
#include <cuda_runtime.h>
#include <math.h>

#define BB 64
#define HH 14
#define WW 14
#define CC 32
#define OO 10
#define NN (HH*WW*CC)          /* 6272 */
#define SPT 196
#define PTOT (BB*SPT)          /* 12544 */
#define NBLK 148               /* persistent blocks, one per SM */
#define MAXN 85
#define G 8
#define EPSV 1e-9f
#define LOG2E 1.4426950408889634f
#define LN2PI 1.8378770664093453f

/* double-buffered cross-block partials: [parity][blk][seg][o][33] */
__device__ float g_part[2][NBLK*2*OO*33];
/* per-block moment stats for factored IT0: [blk][stat][c] */
__device__ float g_mst[NBLK][72*CC];
__device__ unsigned int g_ctr;
__device__ unsigned int g_epoch;

typedef unsigned long long u64;
__device__ __forceinline__ u64 pk2(float lo, float hi){ u64 r; asm("mov.b64 %0,{%1,%2};" :"=l"(r):"f"(lo),"f"(hi)); return r; }
__device__ __forceinline__ void upk2(u64 a, float& lo, float& hi){ asm("mov.b64 {%0,%1},%2;":"=f"(lo),"=f"(hi):"l"(a)); }
__device__ __forceinline__ u64 fma2(u64 a,u64 b,u64 c){ u64 r; asm("fma.rn.f32x2 %0,%1,%2,%3;":"=l"(r):"l"(a),"l"(b),"l"(c)); return r; }
__device__ __forceinline__ u64 add2(u64 a,u64 b){ u64 r; asm("add.rn.f32x2 %0,%1,%2;":"=l"(r):"l"(a),"l"(b)); return r; }
__device__ __forceinline__ u64 mul2(u64 a,u64 b){ u64 r; asm("mul.rn.f32x2 %0,%1,%2;":"=l"(r):"l"(a),"l"(b)); return r; }
__device__ __forceinline__ float ex2f(float x){ float r; asm("ex2.approx.f32 %0,%1;":"=f"(r):"f"(x)); return r; }
__device__ __forceinline__ float rcpf(float x){ float r; asm("rcp.approx.f32 %0,%1;":"=f"(r):"f"(x)); return r; }

struct Shm {
    float  act [MAXN*CC];        /* 10880 B */
    float  sbuf[G*CC*18];        /* 18432 B : pair-swizzled pose, stride 18 */
    u64    offs[MAXN+3];
    float  lgb [4*OO*33];
    float2 mrs [4*CC];
    u64    A2pk[2*OO*8];         /* [seg][o][p*4+k] packed -0.5/var*log2e */
    u64    Mpk [2*OO*8];         /* packed -mu */
    float  Mu  [2*OO*16];
    float  C0  [2*OO];
    unsigned e0;
};

__device__ __forceinline__ void grid_barrier(unsigned target_epoch){
    __threadfence();
    __syncthreads();
    if (threadIdx.x == 0 && threadIdx.y == 0){
        unsigned a = atomicAdd(&g_ctr, 1u);
        if (a == NBLK-1u){
            atomicExch(&g_ctr, 0u);
            __threadfence();
            atomicAdd(&g_epoch, 1u);
        } else {
            while ((int)(*(volatile unsigned*)&g_epoch) - (int)target_epoch < 0) { }
        }
    }
    __syncthreads();
}

__device__ __forceinline__ void ldg_rows(const float4* pb4, int g, int t,
                                         float4& p0, float4& p1, float4& p2, float4& p3){
    const float4* s = pb4 + ((size_t)g*G*CC + t)*4;
    p0 = s[0]; p1 = s[1]; p2 = s[2]; p3 = s[3];
}
/* +1 float2 shift for rows with bit4 set: kills c <-> c+16 bank conflicts */
__device__ __forceinline__ void sts_row(float* slotbuf, int t,
                                        const float4& p0, const float4& p1,
                                        const float4& p2, const float4& p3){
    float2* sb2 = (float2*)&slotbuf[t*18 + 2*((t>>4)&1)];
    sb2[0] = make_float2(p0.x, p1.x);
    sb2[1] = make_float2(p0.y, p1.y);
    sb2[2] = make_float2(p0.z, p1.z);
    sb2[3] = make_float2(p0.w, p1.w);
    sb2[4] = make_float2(p2.x, p3.x);
    sb2[5] = make_float2(p2.y, p3.y);
    sb2[6] = make_float2(p2.z, p3.z);
    sb2[7] = make_float2(p2.w, p3.w);
}

__device__ __forceinline__ void load_soft_consts(Shm* sh, int seg, int o,
        u64 A2[2][4], u64 nMU[2][4], float& C0v){
    C0v = sh->C0[seg*OO + o];
#pragma unroll
    for (int p = 0; p < 2; p++)
#pragma unroll
    for (int k = 0; k < 4; k++){
        A2[p][k]  = sh->A2pk[seg*OO*8 + o*8 + p*4 + k];
        nMU[p][k] = sh->Mpk [seg*OO*8 + o*8 + p*4 + k];
    }
}

__device__ __forceinline__ void reduce_store(float* gpbase, int o, int c,
                                             float S0, const u64 S1[2][4], const u64 S2[2][4]){
    float f[33];
#pragma unroll
    for (int p = 0; p < 2; p++)
#pragma unroll
    for (int k = 0; k < 4; k++){
        upk2(S1[p][k], f[p*8+k],    f[p*8+4+k]);
        upk2(S2[p][k], f[16+p*8+k], f[16+p*8+4+k]);
    }
    f[32] = S0;
#pragma unroll
    for (int off = 16; off > 0; off >>= 1){
#pragma unroll
        for (int i = 0; i < 33; i++)
            f[i] += __shfl_down_sync(0xffffffffu, f[i], off);
    }
    if (c == 0){
#pragma unroll
        for (int i = 0; i < 33; i++) gpbase[o*33 + i] = f[i];
    }
}

/* batch of pts (1..4) points: sweep1 (votes->u, logits), parallel reducers,
   sweep2 (rr, accumulate). Static unroll, predicated on lp < pts. */
__device__ __forceinline__ void process_batch(
    Shm* sh, int row0, int gpt0, int pts,
    const u64 wpk[4][4], const u64 A2[2][4], const u64 nMU[2][4], float C0v,
    int c, int o, float& S0, u64 S1[2][4], u64 S2[2][4])
{
    u64 u[4][2][4];
    float lg[4];
    const int csh = (c>>4)&1;

#pragma unroll
    for (int lp = 0; lp < 4; lp++){
        if (lp < pts){
            const u64* q = (const u64*)(sh->sbuf) + ((size_t)(row0+lp)*CC + c)*9 + csh;
            const u64 j0a = q[0], j1a = q[1], j2a = q[2], j3a = q[3];
            const u64 j0b = q[4], j1b = q[5], j2b = q[6], j3b = q[7];
#pragma unroll
            for (int k = 0; k < 4; k++){
                u64 a0 = fma2(j0a, wpk[0][k], nMU[0][k]);
                u64 a1 = fma2(j0b, wpk[0][k], nMU[1][k]);
                a0 = fma2(j1a, wpk[1][k], a0);
                a1 = fma2(j1b, wpk[1][k], a1);
                a0 = fma2(j2a, wpk[2][k], a0);
                a1 = fma2(j2b, wpk[2][k], a1);
                a0 = fma2(j3a, wpk[3][k], a0);
                a1 = fma2(j3b, wpk[3][k], a1);
                u[lp][0][k] = a0; u[lp][1][k] = a1;
            }
            u[lp][0][3] = add2(u[lp][0][3], sh->offs[gpt0+lp]);

            u64 q2, l2;
            q2 = mul2(u[lp][0][0], u[lp][0][0]); l2 = mul2(q2, A2[0][0]);
            q2 = mul2(u[lp][0][1], u[lp][0][1]); l2 = fma2(q2, A2[0][1], l2);
            q2 = mul2(u[lp][0][2], u[lp][0][2]); l2 = fma2(q2, A2[0][2], l2);
            q2 = mul2(u[lp][0][3], u[lp][0][3]); l2 = fma2(q2, A2[0][3], l2);
            q2 = mul2(u[lp][1][0], u[lp][1][0]); l2 = fma2(q2, A2[1][0], l2);
            q2 = mul2(u[lp][1][1], u[lp][1][1]); l2 = fma2(q2, A2[1][1], l2);
            q2 = mul2(u[lp][1][2], u[lp][1][2]); l2 = fma2(q2, A2[1][2], l2);
            q2 = mul2(u[lp][1][3], u[lp][1][3]); l2 = fma2(q2, A2[1][3], l2);
            float x, y; upk2(l2, x, y);
            lg[lp] = C0v + (x + y);
            sh->lgb[lp*(OO*33) + o*33 + c] = lg[lp];
        }
    }

    __syncthreads();
    if (o < pts){
        const float* lb = sh->lgb + o*(OO*33) + c;
        float lv[OO];
#pragma unroll
        for (int oo = 0; oo < OO; oo++) lv[oo] = lb[oo*33];
        const float m01 = fmaxf(lv[0], lv[1]);
        const float m23 = fmaxf(lv[2], lv[3]);
        const float m45 = fmaxf(lv[4], lv[5]);
        const float m67 = fmaxf(lv[6], lv[7]);
        const float m89 = fmaxf(lv[8], lv[9]);
        const float m = fmaxf(fmaxf(fmaxf(m01, m23), fmaxf(m45, m67)), m89);
        float e0 = ex2f(lv[0]-m), e1 = ex2f(lv[1]-m);
        float e2 = ex2f(lv[2]-m), e3 = ex2f(lv[3]-m);
        float e4 = ex2f(lv[4]-m), e5 = ex2f(lv[5]-m);
        float e6 = ex2f(lv[6]-m), e7 = ex2f(lv[7]-m);
        float e8 = ex2f(lv[8]-m), e9 = ex2f(lv[9]-m);
        const float s = (((e0+e1)+(e2+e3)) + ((e4+e5)+(e6+e7))) + (e8+e9);
        sh->mrs[o*CC + c] = make_float2(m, rcpf(s));
    }
    __syncthreads();

    float2 mr[4]; float av[4];
#pragma unroll
    for (int lp = 0; lp < 4; lp++){
        if (lp < pts){
            mr[lp] = sh->mrs[lp*CC + c];
            av[lp] = sh->act[(gpt0+lp)*CC + c];
        }
    }
#pragma unroll
    for (int lp = 0; lp < 4; lp++){
        if (lp < pts){
            const float rr = ex2f(lg[lp] - mr[lp].x) * mr[lp].y;
            const float rp = rr * av[lp];
            S0 += rp;
            const u64 rk = pk2(rp, rp);
#pragma unroll
            for (int p = 0; p < 2; p++)
#pragma unroll
            for (int k = 0; k < 4; k++){
                const u64 ru = mul2(rk, u[lp][p][k]);
                S1[p][k] = add2(S1[p][k], ru);
                S2[p][k] = fma2(ru, u[lp][p][k], S2[p][k]);
            }
        }
    }
}

/* soft pass: n points, boundary pbrel splits seg0/seg1 (uniform across block) */
__device__ __forceinline__ void stats_pass_soft(
    const float* __restrict__ pose_blk, Shm* sh,
    const u64 wpk[4][4], int c, int o, int n, int pbrel, int nseg,
    float* gp0, float* gp1)
{
    u64 A2[2][4], nMU[2][4]; float C0v;
    load_soft_consts(sh, 0, o, A2, nMU, C0v);

    u64 S1[2][4], S2[2][4]; float S0 = 0.f;
#pragma unroll
    for (int p = 0; p < 2; p++)
#pragma unroll
    for (int k = 0; k < 4; k++){ S1[p][k] = 0ull; S2[p][k] = 0ull; }

    const int t = o*32 + c;
    const float4* pb4 = (const float4*)pose_blk;
    const int ngrp = (n + G - 1)/G;

    float4 pr0, pr1, pr2, pr3;
    {
        const int pts0 = (n < G) ? n : G;
        if (t < pts0*CC) ldg_rows(pb4, 0, t, pr0, pr1, pr2, pr3);
    }

    for (int g = 0; g < ngrp; g++){
        const int gend = ((g+1)*G < n) ? (g+1)*G : n;
        const int rows = (gend - g*G)*CC;
        if (t < rows) sts_row(sh->sbuf, t, pr0, pr1, pr2, pr3);
        __syncthreads();
        if (g < ngrp-1){
            const int ne = ((g+2)*G < n) ? (g+2)*G : n;
            if (t < (ne - (g+1)*G)*CC) ldg_rows(pb4, g+1, t, pr0, pr1, pr2, pr3);
        }

        int pos = g*G;
        while (pos < gend){
            if (pos == pbrel){               /* uniform: flush seg0, switch consts */
                reduce_store(gp0, o, c, S0, S1, S2);
                S0 = 0.f;
#pragma unroll
                for (int p = 0; p < 2; p++)
#pragma unroll
                for (int k = 0; k < 4; k++){ S1[p][k] = 0ull; S2[p][k] = 0ull; }
                load_soft_consts(sh, 1, o, A2, nMU, C0v);
            }
            const int lim = (pos < pbrel) ? ((gend < pbrel) ? gend : pbrel) : gend;
            int pts = lim - pos; if (pts > 4) pts = 4;
            process_batch(sh, pos - g*G, pos, pts, wpk, A2, nMU, C0v, c, o, S0, S1, S2);
            pos += pts;
        }
    }
    reduce_store((nseg == 2) ? gp1 : gp0, o, c, S0, S1, S2);
}

/* moment accumulation per point (o selects the stat subset; uniform per warp) */
#define MOMACC(ACC, a, q2, offv) do { \
    if (o < 4){ \
        const int bs = (o >> 1) << 2; \
        const float2 a0 = q2[bs], a1 = q2[bs+1], a2 = q2[bs+2], a3 = q2[bs+3]; \
        const float p0 = (o & 1) ? a0.y : a0.x; \
        const float p1 = (o & 1) ? a1.y : a1.x; \
        const float p2 = (o & 1) ? a2.y : a2.x; \
        const float p3 = (o & 1) ? a3.y : a3.x; \
        const float t0 = (a)*p0, t1 = (a)*p1, t2 = (a)*p2, t3 = (a)*p3; \
        ACC[0]=fmaf(t0,p0,ACC[0]); ACC[1]=fmaf(t0,p1,ACC[1]); \
        ACC[2]=fmaf(t0,p2,ACC[2]); ACC[3]=fmaf(t0,p3,ACC[3]); \
        ACC[4]=fmaf(t1,p1,ACC[4]); ACC[5]=fmaf(t1,p2,ACC[5]); \
        ACC[6]=fmaf(t1,p3,ACC[6]); ACC[7]=fmaf(t2,p2,ACC[7]); \
        ACC[8]=fmaf(t2,p3,ACC[8]); ACC[9]=fmaf(t3,p3,ACC[9]); \
    } else if (o < 6){ \
        const int bs = (o == 5) ? 4 : 0; \
        const float2 a0 = q2[bs], a1 = q2[bs+1], a2 = q2[bs+2], a3 = q2[bs+3]; \
        ACC[0]=fmaf((a),a0.x,ACC[0]); ACC[1]=fmaf((a),a1.x,ACC[1]); \
        ACC[2]=fmaf((a),a2.x,ACC[2]); ACC[3]=fmaf((a),a3.x,ACC[3]); \
        ACC[4]=fmaf((a),a0.y,ACC[4]); ACC[5]=fmaf((a),a1.y,ACC[5]); \
        ACC[6]=fmaf((a),a2.y,ACC[6]); ACC[7]=fmaf((a),a3.y,ACC[7]); \
    } else if (o == 6){ \
        float ow, oh; upk2(offv, ow, oh); \
        ACC[0] += (a); \
        ACC[1] = fmaf((a), ow, ACC[1]); \
        ACC[2] = fmaf((a), oh, ACC[2]); \
        ACC[3] = fmaf((a)*ow, ow, ACC[3]); \
        ACC[4] = fmaf((a)*oh, oh, ACC[4]); \
    } else if (o == 7){ \
        float ow, oh; upk2(offv, ow, oh); \
        const float aw = (a)*ow; \
        const float2 a0 = q2[0], a1 = q2[1], a2 = q2[2], a3 = q2[3]; \
        ACC[0]=fmaf(aw,a0.x,ACC[0]); ACC[1]=fmaf(aw,a1.x,ACC[1]); \
        ACC[2]=fmaf(aw,a2.x,ACC[2]); ACC[3]=fmaf(aw,a3.x,ACC[3]); \
    } else if (o == 8){ \
        float ow, oh; upk2(offv, ow, oh); \
        const float ah = (a)*oh; \
        const float2 a0 = q2[0], a1 = q2[1], a2 = q2[2], a3 = q2[3]; \
        ACC[0]=fmaf(ah,a0.y,ACC[0]); ACC[1]=fmaf(ah,a1.y,ACC[1]); \
        ACC[2]=fmaf(ah,a2.y,ACC[2]); ACC[3]=fmaf(ah,a3.y,ACC[3]); \
    } \
} while(0)

#define MOMPUB(ACC, mst) do { \
    if (o < 4){ \
        for (int s = 0; s < 10; s++) mst[(16 + o*10 + s)*CC + c] = ACC[s]; \
    } else if (o == 4){ \
        for (int s = 0; s < 8; s++) mst[s*CC + c] = ACC[s]; \
    } else if (o == 5){ \
        for (int s = 0; s < 8; s++) mst[(8+s)*CC + c] = ACC[s]; \
    } else if (o == 6){ \
        for (int s = 0; s < 5; s++) mst[(56+s)*CC + c] = ACC[s]; \
    } else if (o == 7){ \
        for (int s = 0; s < 4; s++) mst[(61+s)*CC + c] = ACC[s]; \
    } else if (o == 8){ \
        for (int s = 0; s < 4; s++) mst[(65+s)*CC + c] = ACC[s]; \
    } \
} while(0)

__device__ __forceinline__ void contract_store(const float* mst, const float* wmat,
                                               int c, int o, float* gpbase)
{
    float wv[4][4];
#pragma unroll
    for (int j = 0; j < 4; j++)
#pragma unroll
    for (int k = 0; k < 4; k++)
        wv[j][k] = wmat[((size_t)(c*OO + o))*16 + j*4 + k];

    float Mp[16];
#pragma unroll
    for (int s = 0; s < 16; s++) Mp[s] = mst[s*CC + c];
    float Mpp[40];
#pragma unroll
    for (int s = 0; s < 40; s++) Mpp[s] = mst[(16+s)*CC + c];
    const float M0  = mst[56*CC + c];
    const float Mw  = mst[57*CC + c];
    const float Mh  = mst[58*CC + c];
    const float Mw2 = mst[59*CC + c];
    const float Mh2 = mst[60*CC + c];
    float Mwp[4], Mhp[4];
#pragma unroll
    for (int s = 0; s < 4; s++){ Mwp[s] = mst[(61+s)*CC + c]; Mhp[s] = mst[(65+s)*CC + c]; }

    float f[33];
#pragma unroll
    for (int i = 0; i < 4; i++)
#pragma unroll
    for (int k = 0; k < 4; k++){
        float s = Mp[i*4+0]*wv[0][k];
        s = fmaf(Mp[i*4+1], wv[1][k], s);
        s = fmaf(Mp[i*4+2], wv[2][k], s);
        s = fmaf(Mp[i*4+3], wv[3][k], s);
        f[i*4+k] = s;
    }
    f[3] += Mw; f[7] += Mh;
#pragma unroll
    for (int k = 0; k < 4; k++){
        float pr[10];
        pr[0] = wv[0][k]*wv[0][k];
        pr[1] = 2.f*wv[0][k]*wv[1][k];
        pr[2] = 2.f*wv[0][k]*wv[2][k];
        pr[3] = 2.f*wv[0][k]*wv[3][k];
        pr[4] = wv[1][k]*wv[1][k];
        pr[5] = 2.f*wv[1][k]*wv[2][k];
        pr[6] = 2.f*wv[1][k]*wv[3][k];
        pr[7] = wv[2][k]*wv[2][k];
        pr[8] = 2.f*wv[2][k]*wv[3][k];
        pr[9] = wv[3][k]*wv[3][k];
#pragma unroll
        for (int i = 0; i < 4; i++){
            const float* mp = Mpp + i*10;
            float s = mp[0]*pr[0];
#pragma unroll
            for (int tt = 1; tt < 10; tt++) s = fmaf(mp[tt], pr[tt], s);
            f[16 + i*4 + k] = s;
        }
    }
    {
        float cw = Mwp[0]*wv[0][3];
        cw = fmaf(Mwp[1], wv[1][3], cw);
        cw = fmaf(Mwp[2], wv[2][3], cw);
        cw = fmaf(Mwp[3], wv[3][3], cw);
        f[16+3] += 2.f*cw + Mw2;
        float ch = Mhp[0]*wv[0][3];
        ch = fmaf(Mhp[1], wv[1][3], ch);
        ch = fmaf(Mhp[2], wv[2][3], ch);
        ch = fmaf(Mhp[3], wv[3][3], ch);
        f[16+7] += 2.f*ch + Mh2;
    }
    f[32] = 0.1f*M0;
#pragma unroll
    for (int s = 0; s < 32; s++) f[s] *= 0.1f;

#pragma unroll
    for (int off = 16; off > 0; off >>= 1){
#pragma unroll
        for (int i = 0; i < 33; i++)
            f[i] += __shfl_down_sync(0xffffffffu, f[i], off);
    }
    if (c == 0){
#pragma unroll
        for (int i = 0; i < 33; i++) gpbase[o*33 + i] = f[i];
    }
}

__device__ __forceinline__ void stats_zero_fact(
    const float* __restrict__ pose_blk, Shm* sh, const float* __restrict__ wmat,
    int c, int o, int n, int pbrel, int nseg, float* gp0, float* gp1, int blk)
{
    float acc0[10], acc1[10];
#pragma unroll
    for (int i = 0; i < 10; i++){ acc0[i] = 0.f; acc1[i] = 0.f; }

    const int t = o*32 + c;
    const float4* pb4 = (const float4*)pose_blk;
    const int ngrp = (n + G - 1)/G;
    const int csh = (c>>4)&1;

    float4 pr0, pr1, pr2, pr3;
    {
        const int pts0 = (n < G) ? n : G;
        if (t < pts0*CC) ldg_rows(pb4, 0, t, pr0, pr1, pr2, pr3);
    }

    for (int g = 0; g < ngrp; g++){
        const int gend = ((g+1)*G < n) ? (g+1)*G : n;
        const int pts = gend - g*G;
        if (t < pts*CC) sts_row(sh->sbuf, t, pr0, pr1, pr2, pr3);
        __syncthreads();
        if (g < ngrp-1){
            const int ne = ((g+2)*G < n) ? (g+2)*G : n;
            if (t < (ne - (g+1)*G)*CC) ldg_rows(pb4, g+1, t, pr0, pr1, pr2, pr3);
        }

        for (int lp = 0; lp < pts; lp++){
            const int p = g*G + lp;
            const float a = sh->act[p*CC + c];
            const float2* q2 = (const float2*)(sh->sbuf) + ((size_t)lp*CC + c)*9 + csh;
            const u64 offv = sh->offs[p];
            if (p < pbrel){ MOMACC(acc0, a, q2, offv); }
            else          { MOMACC(acc1, a, q2, offv); }
        }
        __syncthreads();
    }

    float* mst = g_mst[blk];
    MOMPUB(acc0, mst);
    __syncthreads();
    contract_store(mst, wmat, c, o, gp0);
    if (nseg == 2){
        __syncthreads();
        MOMPUB(acc1, mst);
        __syncthreads();
        contract_store(mst, wmat, c, o, gp1);
    }
}

__device__ __forceinline__ void block_finalize(
    int it, int b0, int nseg, int tid, Shm* sh,
    const float* __restrict__ beta_a, const float* __restrict__ beta_u,
    float* __restrict__ out)
{
    const int seg = tid / 160;
    if (seg == 0 || nseg == 2){
        const int r = tid - seg*160;
        const int o = r >> 4, d = r & 15;
        const int b = b0 + seg;

        const float* buf = g_part[it & 1];
        const int jlo = (29008*b + 147)/12544;
        const int jhi = (29008*b + 29007)/12544;
        float T1 = 0.f, T2 = 0.f, S0 = 0.f;
        for (int jj = jlo; jj <= jhi; jj++){
            const int p0j = (3136*jj)/37;
            const int s = b - p0j/SPT;
            const float* gp = buf + ((size_t)(jj*2 + s)*OO + o)*33;
            T1 += __ldcg(gp + d);
            T2 += __ldcg(gp + 16 + d);
            S0 += __ldcg(gp + 32);
        }
        const float mu_prev = (it == 0) ? 0.f : sh->Mu[seg*OO*16 + o*16 + d];

        /* exact shifted-moment identity in fp64 (cancellation-safe) */
        const double S0d = (double)S0;
        const double rsd = S0d + (double)EPSV;
        const double S1d = (double)T1 + (double)mu_prev * S0d;
        const double mud = S1d / rsd;
        const double e   = mud - (double)mu_prev;
        double varnum = (double)T2 - 2.0*e*(double)T1 + e*e*S0d;
        if (varnum < 0.0) varnum = 0.0;
        const double vard = varnum / rsd + (double)EPSV;

        const float mu   = (float)mud;
        const float var  = (float)vard;
        const float lvar = logf(var);
        const float iv   = 1.0f/var;
        const float rs   = (float)rsd;

        float r1 = lvar;
#pragma unroll
        for (int m = 8; m > 0; m >>= 1)
            r1 += __shfl_xor_sync(0xffffffffu, r1, m);

        const float cost     = rs * (16.0f*beta_u[o] + 0.5f*r1);
        const float inv_temp = 1.0f + (float)it;
        const float z        = inv_temp * (beta_a[o] - cost);
        const float actv     = 1.0f / (1.0f + expf(-z));

        if (it < 2){
            const int p = d >> 3, hi = (d >> 2) & 1, k = d & 3;
            ((float*)&sh->A2pk[seg*OO*8 + o*8 + p*4 + k])[hi] = -0.5f*iv*LOG2E;
            ((float*)&sh->Mpk [seg*OO*8 + o*8 + p*4 + k])[hi] = -mu;
            sh->Mu[seg*OO*16 + o*16 + d] = mu;
            if (d == 0)
                sh->C0[seg*OO + o] = (logf(actv + EPSV) - 0.5f*(16.0f*LN2PI + r1)) * LOG2E;
        } else {
            out[(b*OO + o)*16 + d] = mu;
            if (d == 0) out[BB*OO*16 + b*OO + o] = actv;
        }
    }
    __syncthreads();
}

__global__ __launch_bounds__(320)
void fccaps_kernel(const float* __restrict__ pose,
                   const float* __restrict__ act,
                   const float* __restrict__ wmat,
                   const float* __restrict__ beta_a,
                   const float* __restrict__ beta_u,
                   float* __restrict__ out)
{
    __shared__ Shm sh;

    const int c   = threadIdx.x;
    const int o   = threadIdx.y;
    const int tid = o*32 + c;
    const int j   = blockIdx.x;

    const int p0 = (3136*j)/37;
    const int p1 = (3136*(j+1))/37;
    const int n  = p1 - p0;                       /* 84 or 85 */
    const int b0 = p0 / SPT;
    int pbrel = SPT*(b0+1) - p0;
    const int nseg = (pbrel < n) ? 2 : 1;
    if (pbrel > n) pbrel = n;

    for (int i = tid; i < n*CC; i += 320)
        sh.act[i] = act[(size_t)p0*CC + i];
    if (tid < n){
        const int s = (p0 + tid) % SPT;
        sh.offs[tid] = pk2(((s % WW) + 0.5f)*(1.0f/WW),
                           ((s / WW) + 0.5f)*(1.0f/HH));
    }
    if (tid == 0) sh.e0 = *(volatile unsigned*)&g_epoch;

    u64 wpk[4][4];
#pragma unroll
    for (int jj = 0; jj < 4; jj++)
#pragma unroll
    for (int k = 0; k < 4; k++){
        const float wv = wmat[((size_t)(c*OO + o))*16 + jj*4 + k];
        wpk[jj][k] = pk2(wv, wv);
    }
    __syncthreads();
    const unsigned e0 = sh.e0;

    const float* pose_blk = pose + (size_t)p0*CC*16;
    float* gp0a = &g_part[0][(size_t)(j*2 + 0)*OO*33];
    float* gp1a = &g_part[0][(size_t)(j*2 + 1)*OO*33];
    float* gp0b = &g_part[1][(size_t)(j*2 + 0)*OO*33];
    float* gp1b = &g_part[1][(size_t)(j*2 + 1)*OO*33];

    stats_zero_fact(pose_blk, &sh, wmat, c, o, n, pbrel, nseg, gp0a, gp1a, j);
    grid_barrier(e0 + 1);
    block_finalize(0, b0, nseg, tid, &sh, beta_a, beta_u, out);

    stats_pass_soft(pose_blk, &sh, wpk, c, o, n, pbrel, nseg, gp0b, gp1b);
    grid_barrier(e0 + 2);
    block_finalize(1, b0, nseg, tid, &sh, beta_a, beta_u, out);

    stats_pass_soft(pose_blk, &sh, wpk, c, o, n, pbrel, nseg, gp0a, gp1a);
    grid_barrier(e0 + 3);
    block_finalize(2, b0, nseg, tid, &sh, beta_a, beta_u, out);
}

extern "C" void kernel_launch(void* const* d_in, const int* in_sizes, int n_in,
                              void* d_out, int out_size)
{
    const float* pose = (const float*)d_in[0];  // (B,H,W,C,16)
    const float* actv = (const float*)d_in[1];  // (B,H,W,C,1)
    const float* wmat = (const float*)d_in[2];  // (C,O,4,4)
    const float* ba   = (const float*)d_in[3];  // (1,1,O,1)
    const float* bu   = (const float*)d_in[4];  // (1,1,O,1)
    float* out = (float*)d_out;                 // pose(B,O,16) then act(B,O)

    dim3 blk(32, 10);
    fccaps_kernel<<<NBLK, blk>>>(pose, actv, wmat, ba, bu, out);
}

// round 16
// speedup vs baseline: 1.2551x; 1.2551x over previous
#include <cuda_runtime.h>
#include <math.h>

#define BB 64
#define HH 14
#define WW 14
#define CC 32
#define OO 10
#define NN (HH*WW*CC)          /* 6272 */
#define HALF_S 98
#define NBLK 128               /* persistent blocks */
#define G 8                    /* points per staged group */
#define NGRP 13                /* 12 groups of 8 + one of 2 */
#define EPSV 1e-9f
#define LOG2E 1.4426950408889634f
#define LN2PI 1.8378770664093453f

/* double-buffered cross-block partials: [parity][half][b][o][33] */
__device__ float g_part[2][2*BB*OO*33];
/* per-block moment stats for factored IT0: [blk][stat][c] */
__device__ float g_mst[NBLK][72*CC];
__device__ unsigned int g_ctr;
__device__ unsigned int g_epoch;

typedef unsigned long long u64;
__device__ __forceinline__ u64 pk2(float lo, float hi){ u64 r; asm("mov.b64 %0,{%1,%2};" :"=l"(r):"f"(lo),"f"(hi)); return r; }
__device__ __forceinline__ void upk2(u64 a, float& lo, float& hi){ asm("mov.b64 {%0,%1},%2;":"=f"(lo),"=f"(hi):"l"(a)); }
__device__ __forceinline__ u64 fma2(u64 a,u64 b,u64 c){ u64 r; asm("fma.rn.f32x2 %0,%1,%2,%3;":"=l"(r):"l"(a),"l"(b),"l"(c)); return r; }
__device__ __forceinline__ u64 add2(u64 a,u64 b){ u64 r; asm("add.rn.f32x2 %0,%1,%2;":"=l"(r):"l"(a),"l"(b)); return r; }
__device__ __forceinline__ u64 mul2(u64 a,u64 b){ u64 r; asm("mul.rn.f32x2 %0,%1,%2;":"=l"(r):"l"(a),"l"(b)); return r; }
__device__ __forceinline__ float ex2f(float x){ float r; asm("ex2.approx.f32 %0,%1;":"=f"(r):"f"(x)); return r; }
__device__ __forceinline__ float rcpf(float x){ float r; asm("rcp.approx.f32 %0,%1;":"=f"(r):"f"(x)); return r; }

struct Shm {
    float  act [HALF_S*CC];      /* 12544 B */
    float  sbuf[G*CC*18];        /* 18432 B : pair-swizzled pose, stride 18,
                                    +2-float shift on rows with c-bit4 set */
    u64    offs[HALF_S];         /* packed {w_off, h_off} */
    float  lgb [4*OO*33];        /* logit exchange, 4 points */
    float2 mrs [4*CC];           /* {max, rcp(sum)} per (point, c) */
    u64    A2pk[OO*8];           /* packed -0.5/var*log2e */
    u64    Mpk [OO*8];           /* packed -mu */
    float  Mu  [OO*16];
    float  C0  [OO];
    unsigned e0;
};

__device__ __forceinline__ void grid_barrier(unsigned target_epoch){
    __threadfence();
    __syncthreads();
    if (threadIdx.x == 0 && threadIdx.y == 0){
        unsigned a = atomicAdd(&g_ctr, 1u);
        if (a == NBLK-1u){
            atomicExch(&g_ctr, 0u);
            __threadfence();
            atomicAdd(&g_epoch, 1u);
        } else {
            while ((int)(*(volatile unsigned*)&g_epoch) - (int)target_epoch < 0) { }
        }
    }
    __syncthreads();
}

/* Process a batch of P points (soft iterations): sweep1 (votes->u, logits) with
   pose loads software-pipelined one point ahead, parallel reducers (tree
   max/sum), sweep2 (rr, accumulate). u lives in registers between sweeps. */
template<int P>
__device__ __forceinline__ void process_batch(
    Shm* sh, int gpt0, int lpt0,
    const u64 wpk[4][4], const u64 A2[2][4], const u64 nMU[2][4], float C0,
    int c, int o, int csh, float& S0, u64 S1[2][4], u64 S2[2][4])
{
    u64 u[P][2][4];
    float lg[P];
    u64 pp[2][8];                 /* double-buffered pose, 8 u64 per point */

    {
        const u64* s = (const u64*)(sh->sbuf) + ((size_t)lpt0*CC + c)*9 + csh;
#pragma unroll
        for (int i = 0; i < 8; i++) pp[0][i] = s[i];
    }

    /* ---- sweep 1: votes -> u (centered), logits ---- */
#pragma unroll
    for (int lp = 0; lp < P; lp++){
        if (lp + 1 < P){
            const u64* s = (const u64*)(sh->sbuf) + ((size_t)(lpt0+lp+1)*CC + c)*9 + csh;
#pragma unroll
            for (int i = 0; i < 8; i++) pp[(lp+1)&1][i] = s[i];
        }
        const u64* q = pp[lp&1];
        const u64 j0a = q[0], j1a = q[1], j2a = q[2], j3a = q[3];
        const u64 j0b = q[4], j1b = q[5], j2b = q[6], j3b = q[7];
#pragma unroll
        for (int k = 0; k < 4; k++){
            u64 a0 = fma2(j0a, wpk[0][k], nMU[0][k]);
            u64 a1 = fma2(j0b, wpk[0][k], nMU[1][k]);
            a0 = fma2(j1a, wpk[1][k], a0);
            a1 = fma2(j1b, wpk[1][k], a1);
            a0 = fma2(j2a, wpk[2][k], a0);
            a1 = fma2(j2b, wpk[2][k], a1);
            a0 = fma2(j3a, wpk[3][k], a0);
            a1 = fma2(j3b, wpk[3][k], a1);
            u[lp][0][k] = a0; u[lp][1][k] = a1;
        }
        u[lp][0][3] = add2(u[lp][0][3], sh->offs[gpt0+lp]);

        {
            u64 q2, l2;
            q2 = mul2(u[lp][0][0], u[lp][0][0]); l2 = mul2(q2, A2[0][0]);
            q2 = mul2(u[lp][0][1], u[lp][0][1]); l2 = fma2(q2, A2[0][1], l2);
            q2 = mul2(u[lp][0][2], u[lp][0][2]); l2 = fma2(q2, A2[0][2], l2);
            q2 = mul2(u[lp][0][3], u[lp][0][3]); l2 = fma2(q2, A2[0][3], l2);
            q2 = mul2(u[lp][1][0], u[lp][1][0]); l2 = fma2(q2, A2[1][0], l2);
            q2 = mul2(u[lp][1][1], u[lp][1][1]); l2 = fma2(q2, A2[1][1], l2);
            q2 = mul2(u[lp][1][2], u[lp][1][2]); l2 = fma2(q2, A2[1][2], l2);
            q2 = mul2(u[lp][1][3], u[lp][1][3]); l2 = fma2(q2, A2[1][3], l2);
            float x, y; upk2(l2, x, y);
            lg[lp] = C0 + (x + y);
            sh->lgb[lp*(OO*33) + o*33 + c] = lg[lp];
        }
    }

    /* ---- parallel reducers: warp o reduces point o (tree max/sum) ---- */
    __syncthreads();
    if (o < P){
        const float* lb = sh->lgb + o*(OO*33) + c;
        float lv[OO];
#pragma unroll
        for (int oo = 0; oo < OO; oo++) lv[oo] = lb[oo*33];
        const float m01 = fmaxf(lv[0], lv[1]);
        const float m23 = fmaxf(lv[2], lv[3]);
        const float m45 = fmaxf(lv[4], lv[5]);
        const float m67 = fmaxf(lv[6], lv[7]);
        const float m89 = fmaxf(lv[8], lv[9]);
        const float m = fmaxf(fmaxf(fmaxf(m01, m23), fmaxf(m45, m67)), m89);
        float e0 = ex2f(lv[0]-m), e1 = ex2f(lv[1]-m);
        float e2 = ex2f(lv[2]-m), e3 = ex2f(lv[3]-m);
        float e4 = ex2f(lv[4]-m), e5 = ex2f(lv[5]-m);
        float e6 = ex2f(lv[6]-m), e7 = ex2f(lv[7]-m);
        float e8 = ex2f(lv[8]-m), e9 = ex2f(lv[9]-m);
        const float s = (((e0+e1)+(e2+e3)) + ((e4+e5)+(e6+e7))) + (e8+e9);
        sh->mrs[o*CC + c] = make_float2(m, rcpf(s));
    }
    __syncthreads();

    /* ---- sweep 2: rr, accumulate (loads hoisted ahead of ex2) ---- */
    float2 mr[P]; float av[P];
#pragma unroll
    for (int lp = 0; lp < P; lp++){
        mr[lp] = sh->mrs[lp*CC + c];
        av[lp] = sh->act[(gpt0+lp)*CC + c];
    }
#pragma unroll
    for (int lp = 0; lp < P; lp++){
        const float rr = ex2f(lg[lp] - mr[lp].x) * mr[lp].y;
        const float rp = rr * av[lp];
        S0 += rp;
        const u64 rk = pk2(rp, rp);
#pragma unroll
        for (int p = 0; p < 2; p++)
#pragma unroll
        for (int k = 0; k < 4; k++){
            const u64 ru = mul2(rk, u[lp][p][k]);
            S1[p][k] = add2(S1[p][k], ru);
            S2[p][k] = fma2(ru, u[lp][p][k], S2[p][k]);
        }
    }
}

/* staging helper: pair-swizzled STS with +8B shift on rows with bit4 of c set */
__device__ __forceinline__ void sts_row_sw(float* sbuf, int t,
                                           const float4& p0, const float4& p1,
                                           const float4& p2, const float4& p3){
    float2* sb2 = (float2*)&sbuf[t*18 + 2*((t>>4)&1)];
    sb2[0] = make_float2(p0.x, p1.x);
    sb2[1] = make_float2(p0.y, p1.y);
    sb2[2] = make_float2(p0.z, p1.z);
    sb2[3] = make_float2(p0.w, p1.w);
    sb2[4] = make_float2(p2.x, p3.x);
    sb2[5] = make_float2(p2.y, p3.y);
    sb2[6] = make_float2(p2.z, p3.z);
    sb2[7] = make_float2(p2.w, p3.w);
}

/* soft pass (iterations 1 and 2), identical to round-13 structure */
__device__ __forceinline__ void stats_pass_soft(
    const float* __restrict__ pose_blk, Shm* sh,
    const u64 wpk[4][4], int c, int o, float* gp)
{
    u64 A2[2][4], nMU[2][4];
    const float C0 = sh->C0[o];
#pragma unroll
    for (int p = 0; p < 2; p++)
#pragma unroll
    for (int k = 0; k < 4; k++){
        A2[p][k]  = sh->A2pk[o*8 + p*4 + k];
        nMU[p][k] = sh->Mpk [o*8 + p*4 + k];
    }

    u64 S1[2][4], S2[2][4]; float S0 = 0.f;
#pragma unroll
    for (int p = 0; p < 2; p++)
#pragma unroll
    for (int k = 0; k < 4; k++){ S1[p][k] = 0ull; S2[p][k] = 0ull; }

    const int t = o*32 + c;
    const int csh = (c>>4)&1;
    const float4* pb4 = (const float4*)pose_blk;

    float4 pr0, pr1, pr2, pr3;
    if (t < G*CC){
        const float4* s = pb4 + (size_t)t*4;
        pr0 = s[0]; pr1 = s[1]; pr2 = s[2]; pr3 = s[3];
    }

    for (int g = 0; g < NGRP; g++){
        const int pts  = (g == NGRP-1) ? (HALF_S - (NGRP-1)*G) : G;   /* 8 or 2 */
        if (t < pts*CC) sts_row_sw(sh->sbuf, t, pr0, pr1, pr2, pr3);
        __syncthreads();
        if (g < NGRP-1){
            const int npts = (g == NGRP-2) ? (HALF_S - (NGRP-1)*G) : G;
            if (t < npts*CC){
                const float4* s = pb4 + ((size_t)(g+1)*G*CC + t)*4;
                pr0 = s[0]; pr1 = s[1]; pr2 = s[2]; pr3 = s[3];
            }
        }

        if (pts == G){
            process_batch<4>(sh, g*G,     0, wpk, A2, nMU, C0, c, o, csh, S0, S1, S2);
            process_batch<4>(sh, g*G + 4, 4, wpk, A2, nMU, C0, c, o, csh, S0, S1, S2);
        } else {
            process_batch<2>(sh, g*G,     0, wpk, A2, nMU, C0, c, o, csh, S0, S1, S2);
        }
    }

    float f[33];
#pragma unroll
    for (int p = 0; p < 2; p++)
#pragma unroll
    for (int k = 0; k < 4; k++){
        upk2(S1[p][k], f[p*8+k],    f[p*8+4+k]);
        upk2(S2[p][k], f[16+p*8+k], f[16+p*8+4+k]);
    }
    f[32] = S0;
#pragma unroll
    for (int off = 16; off > 0; off >>= 1){
#pragma unroll
        for (int i = 0; i < 33; i++)
            f[i] += __shfl_down_sync(0xffffffffu, f[i], off);
    }
    if (c == 0){
#pragma unroll
        for (int i = 0; i < 33; i++) gp[i] = f[i];
    }
}

/* ---------------- factored IT0 (mapping c=tx, o=ty): rr = 0.1 exactly,
   stats are a fixed polynomial in pose moments. Exact algebra vs direct. ---- */
__device__ __forceinline__ void stats_zero_fact(
    const float* __restrict__ pose_blk, Shm* sh,
    const u64 wpk[4][4], int c, int o, float* gp, int blk)
{
    float acc[10];
#pragma unroll
    for (int i = 0; i < 10; i++) acc[i] = 0.f;

    const int t = o*32 + c;
    const int csh = (c>>4)&1;
    const float4* pb4 = (const float4*)pose_blk;

    float4 pr0, pr1, pr2, pr3;
    if (t < G*CC){
        const float4* s = pb4 + (size_t)t*4;
        pr0 = s[0]; pr1 = s[1]; pr2 = s[2]; pr3 = s[3];
    }

    for (int g = 0; g < NGRP; g++){
        const int pts = (g == NGRP-1) ? (HALF_S - (NGRP-1)*G) : G;
        if (t < pts*CC) sts_row_sw(sh->sbuf, t, pr0, pr1, pr2, pr3);
        __syncthreads();
        if (g < NGRP-1){
            const int npts = (g == NGRP-2) ? (HALF_S - (NGRP-1)*G) : G;
            if (t < npts*CC){
                const float4* s = pb4 + ((size_t)(g+1)*G*CC + t)*4;
                pr0 = s[0]; pr1 = s[1]; pr2 = s[2]; pr3 = s[3];
            }
        }

        /* sbuf row layout: float2 slot j = {p[0][j], p[1][j]}, slot 4+j = {p[2][j], p[3][j]} */
        for (int lp = 0; lp < pts; lp++){
            const float a = sh->act[(g*G + lp)*CC + c];
            const float2* q2 = (const float2*)(sh->sbuf) + ((size_t)lp*CC + c)*9 + csh;
            if (o < 4){
                const int bs = (o >> 1) << 2;
                const float2 a0 = q2[bs], a1 = q2[bs+1], a2 = q2[bs+2], a3 = q2[bs+3];
                const float p0 = (o & 1) ? a0.y : a0.x;
                const float p1 = (o & 1) ? a1.y : a1.x;
                const float p2 = (o & 1) ? a2.y : a2.x;
                const float p3 = (o & 1) ? a3.y : a3.x;
                const float t0 = a*p0, t1 = a*p1, t2 = a*p2, t3 = a*p3;
                acc[0]=fmaf(t0,p0,acc[0]); acc[1]=fmaf(t0,p1,acc[1]);
                acc[2]=fmaf(t0,p2,acc[2]); acc[3]=fmaf(t0,p3,acc[3]);
                acc[4]=fmaf(t1,p1,acc[4]); acc[5]=fmaf(t1,p2,acc[5]);
                acc[6]=fmaf(t1,p3,acc[6]); acc[7]=fmaf(t2,p2,acc[7]);
                acc[8]=fmaf(t2,p3,acc[8]); acc[9]=fmaf(t3,p3,acc[9]);
            } else if (o < 6){
                const int bs = (o == 5) ? 4 : 0;
                const float2 a0 = q2[bs], a1 = q2[bs+1], a2 = q2[bs+2], a3 = q2[bs+3];
                acc[0]=fmaf(a,a0.x,acc[0]); acc[1]=fmaf(a,a1.x,acc[1]);
                acc[2]=fmaf(a,a2.x,acc[2]); acc[3]=fmaf(a,a3.x,acc[3]);
                acc[4]=fmaf(a,a0.y,acc[4]); acc[5]=fmaf(a,a1.y,acc[5]);
                acc[6]=fmaf(a,a2.y,acc[6]); acc[7]=fmaf(a,a3.y,acc[7]);
            } else if (o == 6){
                float ow, oh; upk2(sh->offs[g*G+lp], ow, oh);
                acc[0] += a;
                acc[1] = fmaf(a, ow, acc[1]);
                acc[2] = fmaf(a, oh, acc[2]);
                acc[3] = fmaf(a*ow, ow, acc[3]);
                acc[4] = fmaf(a*oh, oh, acc[4]);
            } else if (o == 7){
                float ow, oh; upk2(sh->offs[g*G+lp], ow, oh);
                const float aw = a*ow;
                const float2 a0 = q2[0], a1 = q2[1], a2 = q2[2], a3 = q2[3];
                acc[0]=fmaf(aw,a0.x,acc[0]); acc[1]=fmaf(aw,a1.x,acc[1]);
                acc[2]=fmaf(aw,a2.x,acc[2]); acc[3]=fmaf(aw,a3.x,acc[3]);
            } else if (o == 8){
                float ow, oh; upk2(sh->offs[g*G+lp], ow, oh);
                const float ah = a*oh;
                const float2 a0 = q2[0], a1 = q2[1], a2 = q2[2], a3 = q2[3];
                acc[0]=fmaf(ah,a0.y,acc[0]); acc[1]=fmaf(ah,a1.y,acc[1]);
                acc[2]=fmaf(ah,a2.y,acc[2]); acc[3]=fmaf(ah,a3.y,acc[3]);
            }
        }
        __syncthreads();
    }

    float* mst = g_mst[blk];
    if (o < 4){
#pragma unroll
        for (int s = 0; s < 10; s++) mst[(16 + o*10 + s)*CC + c] = acc[s];
    } else if (o == 4){
#pragma unroll
        for (int s = 0; s < 8; s++) mst[s*CC + c] = acc[s];
    } else if (o == 5){
#pragma unroll
        for (int s = 0; s < 8; s++) mst[(8+s)*CC + c] = acc[s];
    } else if (o == 6){
#pragma unroll
        for (int s = 0; s < 5; s++) mst[(56+s)*CC + c] = acc[s];
    } else if (o == 7){
#pragma unroll
        for (int s = 0; s < 4; s++) mst[(61+s)*CC + c] = acc[s];
    } else if (o == 8){
#pragma unroll
        for (int s = 0; s < 4; s++) mst[(65+s)*CC + c] = acc[s];
    }
    __syncthreads();

    /* contraction per (c,o) */
    float wv[4][4];
#pragma unroll
    for (int j = 0; j < 4; j++)
#pragma unroll
    for (int k = 0; k < 4; k++){ float lo, hi; upk2(wpk[j][k], lo, hi); wv[j][k] = lo; (void)hi; }

    float Mp[16];
#pragma unroll
    for (int s = 0; s < 16; s++) Mp[s] = mst[s*CC + c];
    float Mpp[40];
#pragma unroll
    for (int s = 0; s < 40; s++) Mpp[s] = mst[(16+s)*CC + c];
    const float M0  = mst[56*CC + c];
    const float Mw  = mst[57*CC + c];
    const float Mh  = mst[58*CC + c];
    const float Mw2 = mst[59*CC + c];
    const float Mh2 = mst[60*CC + c];
    float Mwp[4], Mhp[4];
#pragma unroll
    for (int s = 0; s < 4; s++){ Mwp[s] = mst[(61+s)*CC + c]; Mhp[s] = mst[(65+s)*CC + c]; }

    float f[33];
#pragma unroll
    for (int i = 0; i < 4; i++)
#pragma unroll
    for (int k = 0; k < 4; k++){
        float s = Mp[i*4+0]*wv[0][k];
        s = fmaf(Mp[i*4+1], wv[1][k], s);
        s = fmaf(Mp[i*4+2], wv[2][k], s);
        s = fmaf(Mp[i*4+3], wv[3][k], s);
        f[i*4+k] = s;
    }
    f[3] += Mw; f[7] += Mh;
#pragma unroll
    for (int k = 0; k < 4; k++){
        float pr[10];
        pr[0] = wv[0][k]*wv[0][k];
        pr[1] = 2.f*wv[0][k]*wv[1][k];
        pr[2] = 2.f*wv[0][k]*wv[2][k];
        pr[3] = 2.f*wv[0][k]*wv[3][k];
        pr[4] = wv[1][k]*wv[1][k];
        pr[5] = 2.f*wv[1][k]*wv[2][k];
        pr[6] = 2.f*wv[1][k]*wv[3][k];
        pr[7] = wv[2][k]*wv[2][k];
        pr[8] = 2.f*wv[2][k]*wv[3][k];
        pr[9] = wv[3][k]*wv[3][k];
#pragma unroll
        for (int i = 0; i < 4; i++){
            const float* mp = Mpp + i*10;
            float s = mp[0]*pr[0];
#pragma unroll
            for (int tt = 1; tt < 10; tt++) s = fmaf(mp[tt], pr[tt], s);
            f[16 + i*4 + k] = s;
        }
    }
    {
        float cw = Mwp[0]*wv[0][3];
        cw = fmaf(Mwp[1], wv[1][3], cw);
        cw = fmaf(Mwp[2], wv[2][3], cw);
        cw = fmaf(Mwp[3], wv[3][3], cw);
        f[16+3] += 2.f*cw + Mw2;
        float ch = Mhp[0]*wv[0][3];
        ch = fmaf(Mhp[1], wv[1][3], ch);
        ch = fmaf(Mhp[2], wv[2][3], ch);
        ch = fmaf(Mhp[3], wv[3][3], ch);
        f[16+7] += 2.f*ch + Mh2;
    }
    f[32] = 0.1f*M0;
#pragma unroll
    for (int s = 0; s < 32; s++) f[s] *= 0.1f;

#pragma unroll
    for (int off = 16; off > 0; off >>= 1){
#pragma unroll
        for (int i = 0; i < 33; i++)
            f[i] += __shfl_down_sync(0xffffffffu, f[i], off);
    }
    if (c == 0){
#pragma unroll
        for (int i = 0; i < 33; i++) gp[i] = f[i];
    }
}

__device__ __forceinline__ void block_finalize(
    int it, int b, int tid, Shm* sh,
    const float* __restrict__ beta_a, const float* __restrict__ beta_u,
    float* __restrict__ out)
{
    if (tid < 160){
        const int o = tid >> 4, d = tid & 15;
        const float* buf = g_part[it & 1];
        const float* gp0 = &buf[((0*BB + b)*OO + o)*33];
        const float* gp1 = &buf[((1*BB + b)*OO + o)*33];
        const float T1 = __ldcg(gp0 + d)      + __ldcg(gp1 + d);
        const float T2 = __ldcg(gp0 + 16 + d) + __ldcg(gp1 + 16 + d);
        const float S0 = __ldcg(gp0 + 32)     + __ldcg(gp1 + 32);
        const float mu_prev = (it == 0) ? 0.f : sh->Mu[o*16 + d];

        const double S0d = (double)S0;
        const double rsd = S0d + (double)EPSV;
        const double S1d = (double)T1 + (double)mu_prev * S0d;
        const double mud = S1d / rsd;
        const double e   = mud - (double)mu_prev;
        double varnum = (double)T2 - 2.0*e*(double)T1 + e*e*S0d;
        if (varnum < 0.0) varnum = 0.0;
        const double vard = varnum / rsd + (double)EPSV;

        const float mu   = (float)mud;
        const float var  = (float)vard;
        const float lvar = logf(var);
        const float iv   = 1.0f/var;
        const float rs   = (float)rsd;

        float r1 = lvar;
#pragma unroll
        for (int m = 8; m > 0; m >>= 1)
            r1 += __shfl_xor_sync(0xffffffffu, r1, m);

        const float cost     = rs * (16.0f*beta_u[o] + 0.5f*r1);
        const float inv_temp = 1.0f + (float)it;
        const float z        = inv_temp * (beta_a[o] - cost);
        const float actv     = 1.0f / (1.0f + expf(-z));

        if (it < 2){
            const int p = d >> 3, hi = (d >> 2) & 1, k = d & 3;
            ((float*)&sh->A2pk[o*8 + p*4 + k])[hi] = -0.5f*iv*LOG2E;
            ((float*)&sh->Mpk [o*8 + p*4 + k])[hi] = -mu;
            sh->Mu[o*16 + d] = mu;
            if (d == 0)
                sh->C0[o] = (logf(actv + EPSV) - 0.5f*(16.0f*LN2PI + r1)) * LOG2E;
        } else {
            out[(b*OO + o)*16 + d] = mu;
            if (d == 0) out[BB*OO*16 + b*OO + o] = actv;
        }
    }
    __syncthreads();
}

__global__ __launch_bounds__(320)
void fccaps_kernel(const float* __restrict__ pose,
                   const float* __restrict__ act,
                   const float* __restrict__ wmat,
                   const float* __restrict__ beta_a,
                   const float* __restrict__ beta_u,
                   float* __restrict__ out)
{
    __shared__ Shm sh;

    const int c   = threadIdx.x;
    const int o   = threadIdx.y;
    const int tid = o*32 + c;
    const int b    = blockIdx.x >> 1;
    const int half = blockIdx.x & 1;
    const int s0   = half * HALF_S;

    for (int i = tid; i < HALF_S*CC; i += 320)
        sh.act[i] = act[(size_t)b*NN + (size_t)s0*CC + i];
    if (tid < HALF_S){
        const int s = s0 + tid;
        sh.offs[tid] = pk2(((s % WW) + 0.5f)*(1.0f/WW),
                           ((s / WW) + 0.5f)*(1.0f/HH));
    }
    if (tid == 0) sh.e0 = *(volatile unsigned*)&g_epoch;

    u64 wpk[4][4];
#pragma unroll
    for (int j = 0; j < 4; j++)
#pragma unroll
    for (int k = 0; k < 4; k++){
        const float wv = wmat[((size_t)(c*OO + o))*16 + j*4 + k];
        wpk[j][k] = pk2(wv, wv);
    }
    __syncthreads();
    const unsigned e0 = sh.e0;

    const float* pose_blk = pose + ((size_t)b*NN + (size_t)s0*CC)*16;
    const size_t gpi = (((size_t)half*BB + b)*OO + o)*33;

    stats_zero_fact(pose_blk, &sh, wpk, c, o, &g_part[0][gpi], blockIdx.x);
    grid_barrier(e0 + 1);
    block_finalize(0, b, tid, &sh, beta_a, beta_u, out);

    stats_pass_soft(pose_blk, &sh, wpk, c, o, &g_part[1][gpi]);
    grid_barrier(e0 + 2);
    block_finalize(1, b, tid, &sh, beta_a, beta_u, out);

    stats_pass_soft(pose_blk, &sh, wpk, c, o, &g_part[0][gpi]);
    grid_barrier(e0 + 3);
    if (half == 0)
        block_finalize(2, b, tid, &sh, beta_a, beta_u, out);
}

extern "C" void kernel_launch(void* const* d_in, const int* in_sizes, int n_in,
                              void* d_out, int out_size)
{
    const float* pose = (const float*)d_in[0];  // (B,H,W,C,16)
    const float* actv = (const float*)d_in[1];  // (B,H,W,C,1)
    const float* wmat = (const float*)d_in[2];  // (C,O,4,4)
    const float* ba   = (const float*)d_in[3];  // (1,1,O,1)
    const float* bu   = (const float*)d_in[4];  // (1,1,O,1)
    float* out = (float*)d_out;                 // pose(B,O,16) then act(B,O)

    dim3 blk(32, 10);
    fccaps_kernel<<<NBLK, blk>>>(pose, actv, wmat, ba, bu, out);
}